// round 16
// baseline (speedup 1.0000x reference)
#include <cuda_runtime.h>
#include <cuda_bf16.h>
#include <cuda_fp16.h>
#include <cstdint>

#define VOCAB_MAX 100000
#define BL_MAX    12800
#define DIM       128
#define NHEAD     4

// ------------------------- scratch (device globals) -------------------------
__device__ __nv_bfloat16 g_EKbf[VOCAB_MAX * DIM];    // E @ Wk          (bf16)
__device__ __nv_bfloat16 g_EVbf[VOCAB_MAX * DIM];    // E @ (Wv@Wf)     (bf16)
__device__ float g_Esum[VOCAB_MAX];
__device__ float g_Q[BL_MAX * DIM];                  // E[q]@Wq + bq
__device__ float g_QF[BL_MAX * DIM];                 // E[q]@Wf + bv@Wf + bf
__device__ float g_cvec[DIM];                        // bv@Wf + bf
// swizzled fp16 W^T images (n-major, k contiguous, kc ^= n&7)
__device__ uint4 g_WT16[4096];    // [Wk | Wv@Wf]: [n=256][kc=16]
__device__ uint4 g_WQF16[4096];   // [Wq | Wf]:    [n=256][kc=16]

// ------------------------- helpers ------------------------------------------
__device__ __forceinline__ uint32_t smem_to_u32(const void* p) {
    uint32_t a;
    asm("{ .reg .u64 t; cvta.to.shared.u64 t, %1; cvt.u32.u64 %0, t; }" : "=r"(a) : "l"(p));
    return a;
}
__device__ __forceinline__ uint32_t pack_bf2(float lo, float hi) {
    uint32_t r; asm("cvt.rn.bf16x2.f32 %0, %1, %2;" : "=r"(r) : "f"(hi), "f"(lo)); return r;
}
__device__ __forceinline__ uint32_t pack_h2(float lo, float hi) {
    uint32_t r; asm("cvt.rn.f16x2.f32 %0, %1, %2;" : "=r"(r) : "f"(hi), "f"(lo)); return r;
}
__device__ __forceinline__ void ldsm_x4(uint32_t addr, uint32_t* r) {
    asm volatile("ldmatrix.sync.aligned.m8n8.x4.shared.b16 {%0,%1,%2,%3}, [%4];"
                 : "=r"(r[0]), "=r"(r[1]), "=r"(r[2]), "=r"(r[3]) : "r"(addr));
}
__device__ __forceinline__ void mma_f16(float* c, const uint32_t* a, uint32_t b0, uint32_t b1) {
    asm volatile("mma.sync.aligned.m16n8k16.row.col.f32.f16.f16.f32 "
                 "{%0,%1,%2,%3}, {%4,%5,%6,%7}, {%8,%9}, {%0,%1,%2,%3};"
                 : "+f"(c[0]), "+f"(c[1]), "+f"(c[2]), "+f"(c[3])
                 : "r"(a[0]), "r"(a[1]), "r"(a[2]), "r"(a[3]), "r"(b0), "r"(b1));
}
__device__ __forceinline__ float bflo(uint32_t u) { return __uint_as_float(u << 16); }
__device__ __forceinline__ float bfhi(uint32_t u) { return __uint_as_float(u & 0xffff0000u); }

// ------------------------- K0a: Wvf = Wv@Wf (smem-tiled) + cvec --------------
// 16 CTAs x 256 thr; CTA b owns k rows [8b, 8b+8). Wf staged in smem (64KB),
// Wv slice (4KB). Thread: k = 8b + t>>5, n0 = (t&31)*4 -> 4 outputs, written
// directly as fp16 into the VF half (n = 128..255) of g_WT16.
#define WVF_SMEM ((16384 + 1024) * 4)

__global__ void __launch_bounds__(256)
k_wvf(const float* __restrict__ Wv, const float* __restrict__ Wf,
      const float* __restrict__ bv, const float* __restrict__ bf) {
    extern __shared__ float sm[];
    float* sWf = sm;             // [128][128]
    float* sWv = sm + 16384;     // [8][128]
    const int t = threadIdx.x;
    const int b = blockIdx.x;

    for (int i = t; i < 4096; i += 256)
        reinterpret_cast<float4*>(sWf)[i] = reinterpret_cast<const float4*>(Wf)[i];
    if (t < 256)
        reinterpret_cast<float4*>(sWv)[t] =
            reinterpret_cast<const float4*>(Wv + b * 8 * DIM)[t];
    __syncthreads();

    const int kl = t >> 5;               // local k row 0..7
    const int k  = b * 8 + kl;
    const int n0 = (t & 31) * 4;
    float a0 = 0.f, a1 = 0.f, a2 = 0.f, a3 = 0.f;
    #pragma unroll 4
    for (int d = 0; d < 128; d++) {
        float wv = sWv[kl * 128 + d];
        float4 wf = *reinterpret_cast<const float4*>(sWf + d * 128 + n0);
        a0 = fmaf(wv, wf.x, a0);
        a1 = fmaf(wv, wf.y, a1);
        a2 = fmaf(wv, wf.z, a2);
        a3 = fmaf(wv, wf.w, a3);
    }
    unsigned short* img = reinterpret_cast<unsigned short*>(g_WT16);
    float acc[4] = {a0, a1, a2, a3};
    #pragma unroll
    for (int j = 0; j < 4; j++) {
        int n = 128 + n0 + j;
        img[(n * 16 + ((k >> 3) ^ (n & 7))) * 8 + (k & 7)] =
            __half_as_ushort(__float2half(acc[j]));
    }
    if (b == 0 && t < 128) {
        float s = bf[t];
        #pragma unroll 4
        for (int d = 0; d < 128; d++) s = fmaf(bv[d], sWf[d * 128 + t], s);
        g_cvec[t] = s;
    }
}

// ------------------------- K0b: pack Wk / Wq / Wf images ---------------------
__global__ void k_wprep(const float* __restrict__ Wk, const float* __restrict__ Wq,
                        const float* __restrict__ Wf) {
    int u = blockIdx.x * blockDim.x + threadIdx.x;    // 6144 units
    const float* src;
    uint4* dst;
    int n, kc;
    if (u < 2048) {
        n = u & 127; kc = u >> 7;
        src = Wk + n;
        dst = g_WT16 + n * 16 + (kc ^ (n & 7));
    } else if (u < 4096) {
        int v = u - 2048; n = v & 127; kc = v >> 7;
        src = Wq + n;
        dst = g_WQF16 + n * 16 + (kc ^ (n & 7));
    } else if (u < 6144) {
        int v = u - 4096; n = v & 127; kc = v >> 7;
        src = Wf + n;
        int ni = n + 128;
        dst = g_WQF16 + ni * 16 + (kc ^ (ni & 7));
    } else return;
    float f[8];
    #pragma unroll
    for (int i = 0; i < 8; i++) f[i] = src[(size_t)(kc * 8 + i) * DIM];
    uint32_t h[4];
    #pragma unroll
    for (int i = 0; i < 4; i++) h[i] = pack_h2(f[2 * i], f[2 * i + 1]);
    *dst = make_uint4(h[0], h[1], h[2], h[3]);
}

// ------------------------- K1: fused Q/QF gemm + projection ------------------
// Blocks [0, nq): [Q|QF] = gather(E,queries) @ [Wq|Wf]  (M=64 x N=256)
// Blocks [nq, ...): EK|EVF = E @ [Wk|WvWf]              (M=64 x N=256)
#define P_A   0
#define P_B   16384
#define P_OUT 81920
#define PROJ_SMEM 114688

__device__ void gemm_qqf_path(char* smem, uint32_t sb,
                              const float* __restrict__ E,
                              const int* __restrict__ queries,
                              const float* __restrict__ bq, int M, int bx) {
    const int t    = threadIdx.x;
    const int w    = t >> 5;
    const int lane = t & 31;
    const int m0   = bx * 64;

    // stage A: 64 gathered rows (fp16)
    #pragma unroll
    for (int i = 0; i < 2; i++) {
        int u   = t + 512 * i;
        int row = u >> 4;
        int kc  = u & 15;
        int m   = m0 + row;
        int mm  = (m < M) ? m : 0;
        const float4* src = reinterpret_cast<const float4*>(E + (size_t)queries[mm] * DIM + kc * 8);
        float4 f0 = src[0], f1 = src[1];
        uint32_t h0 = pack_h2(f0.x, f0.y), h1 = pack_h2(f0.z, f0.w);
        uint32_t h2 = pack_h2(f1.x, f1.y), h3 = pack_h2(f1.z, f1.w);
        uint32_t off = (uint32_t)row * 256 + (uint32_t)((kc ^ (row & 7)) << 4);
        *reinterpret_cast<uint4*>(smem + P_A + off) = make_uint4(h0, h1, h2, h3);
    }
    // stage B: combined [Wq|Wf] image (64KB)
    {
        uint4* d = reinterpret_cast<uint4*>(smem + P_B);
        #pragma unroll
        for (int i = 0; i < 8; i++) {
            int idx = t + 512 * i;
            d[idx] = g_WQF16[idx];
        }
    }
    __syncthreads();

    const int mg = w & 3;
    const int ng = w >> 2;

    float acc[8][4];
    #pragma unroll
    for (int nt = 0; nt < 8; nt++)
        #pragma unroll
        for (int j = 0; j < 4; j++) acc[nt][j] = 0.f;

    const int aRow  = mg * 16 + ((lane >> 3) & 1) * 8 + (lane & 7);
    const int aKsel = (lane >> 4);
    const int bN    = ng * 64 + ((lane >> 4) & 1) * 8 + (lane & 7);
    const int bKsel = (lane >> 3) & 1;

    #pragma unroll
    for (int ks = 0; ks < 8; ks++) {
        uint32_t a[4];
        {
            int kc = ks * 2 + aKsel;
            ldsm_x4(sb + P_A + aRow * 256 + (((kc ^ (aRow & 7)) << 4)), a);
        }
        {
            uint32_t b[2][4];
            #pragma unroll
            for (int bt = 0; bt < 2; bt++) {
                int n  = bN + bt * 16;
                int kc = ks * 2 + bKsel;
                ldsm_x4(sb + P_B + n * 256 + (((kc ^ (n & 7)) << 4)), b[bt]);
            }
            #pragma unroll
            for (int nt = 0; nt < 4; nt++)
                mma_f16(acc[nt], a, b[nt >> 1][(nt & 1) * 2], b[nt >> 1][(nt & 1) * 2 + 1]);
        }
        {
            uint32_t b[2][4];
            #pragma unroll
            for (int bt = 0; bt < 2; bt++) {
                int n  = bN + (bt + 2) * 16;
                int kc = ks * 2 + bKsel;
                ldsm_x4(sb + P_B + n * 256 + (((kc ^ (n & 7)) << 4)), b[bt]);
            }
            #pragma unroll
            for (int nt = 4; nt < 8; nt++)
                mma_f16(acc[nt], a, b[(nt - 4) >> 1][(nt & 1) * 2], b[(nt - 4) >> 1][(nt & 1) * 2 + 1]);
        }
    }

    // epilogue: fp32 + bias, to g_Q (cols 0..127) / g_QF (cols 128..255)
    const int rl = mg * 16 + (lane >> 2);
    #pragma unroll
    for (int nt = 0; nt < 8; nt++) {
        int col = ng * 64 + nt * 8 + (lane & 3) * 2;
        float b0, b1;
        float* dst;
        if (col < 128) { b0 = bq[col];         b1 = bq[col + 1];         dst = g_Q  + col; }
        else           { b0 = g_cvec[col-128]; b1 = g_cvec[col - 127];   dst = g_QF + (col - 128); }
        int r0 = m0 + rl, r1 = r0 + 8;
        if (r0 < M)
            *reinterpret_cast<float2*>(dst + (size_t)r0 * DIM) =
                make_float2(acc[nt][0] + b0, acc[nt][1] + b1);
        if (r1 < M)
            *reinterpret_cast<float2*>(dst + (size_t)r1 * DIM) =
                make_float2(acc[nt][2] + b0, acc[nt][3] + b1);
    }
}

__global__ void __launch_bounds__(512, 2)
k_proj_mma(const float* __restrict__ E, const int* __restrict__ queries,
           const float* __restrict__ bq, int V, int M, int nq) {
    extern __shared__ char smem[];
    const uint32_t sb = smem_to_u32(smem);
    const int bx = blockIdx.x;

    if (bx < nq) {
        gemm_qqf_path(smem, sb, E, queries, bq, M, bx);
        return;
    }

    const int t    = threadIdx.x;
    const int w    = t >> 5;
    const int lane = t & 31;
    const int v0   = (bx - nq) * 64;

    #pragma unroll
    for (int i = 0; i < 2; i++) {
        int u   = t + 512 * i;
        int row = u >> 4;
        int kc  = u & 15;
        int gr  = v0 + row;
        int grc = (gr < V) ? gr : 0;
        const float4* src = reinterpret_cast<const float4*>(E + (size_t)grc * DIM + kc * 8);
        float4 f0 = __ldcs(src);
        float4 f1 = __ldcs(src + 1);
        uint32_t h0 = pack_h2(f0.x, f0.y), h1 = pack_h2(f0.z, f0.w);
        uint32_t h2 = pack_h2(f1.x, f1.y), h3 = pack_h2(f1.z, f1.w);
        uint32_t off = (uint32_t)row * 256 + (uint32_t)((kc ^ (row & 7)) << 4);
        *reinterpret_cast<uint4*>(smem + P_A + off) = make_uint4(h0, h1, h2, h3);
        float s8 = ((f0.x + f0.y) + (f0.z + f0.w)) + ((f1.x + f1.y) + (f1.z + f1.w));
        s8 += __shfl_xor_sync(0xffffffffu, s8, 8);
        s8 += __shfl_xor_sync(0xffffffffu, s8, 4);
        s8 += __shfl_xor_sync(0xffffffffu, s8, 2);
        s8 += __shfl_xor_sync(0xffffffffu, s8, 1);
        if ((t & 15) == 0 && gr < V) g_Esum[gr] = s8;
    }
    {
        uint4* d = reinterpret_cast<uint4*>(smem + P_B);
        #pragma unroll
        for (int i = 0; i < 8; i++) {
            int idx = t + 512 * i;
            d[idx] = g_WT16[idx];
        }
    }
    __syncthreads();

    const int mg = w & 3;
    const int ng = w >> 2;

    float acc[8][4];
    #pragma unroll
    for (int nt = 0; nt < 8; nt++)
        #pragma unroll
        for (int j = 0; j < 4; j++) acc[nt][j] = 0.f;

    const int aRow  = mg * 16 + ((lane >> 3) & 1) * 8 + (lane & 7);
    const int aKsel = (lane >> 4);
    const int bN    = ng * 64 + ((lane >> 4) & 1) * 8 + (lane & 7);
    const int bKsel = (lane >> 3) & 1;

    #pragma unroll
    for (int ks = 0; ks < 8; ks++) {
        uint32_t a[4];
        {
            int kc = ks * 2 + aKsel;
            ldsm_x4(sb + P_A + aRow * 256 + (((kc ^ (aRow & 7)) << 4)), a);
        }
        {
            uint32_t b[2][4];
            #pragma unroll
            for (int bt = 0; bt < 2; bt++) {
                int n  = bN + bt * 16;
                int kc = ks * 2 + bKsel;
                ldsm_x4(sb + P_B + n * 256 + (((kc ^ (n & 7)) << 4)), b[bt]);
            }
            #pragma unroll
            for (int nt = 0; nt < 4; nt++)
                mma_f16(acc[nt], a, b[nt >> 1][(nt & 1) * 2], b[nt >> 1][(nt & 1) * 2 + 1]);
        }
        {
            uint32_t b[2][4];
            #pragma unroll
            for (int bt = 0; bt < 2; bt++) {
                int n  = bN + (bt + 2) * 16;
                int kc = ks * 2 + bKsel;
                ldsm_x4(sb + P_B + n * 256 + (((kc ^ (n & 7)) << 4)), b[bt]);
            }
            #pragma unroll
            for (int nt = 4; nt < 8; nt++)
                mma_f16(acc[nt], a, b[(nt - 4) >> 1][(nt & 1) * 2], b[(nt - 4) >> 1][(nt & 1) * 2 + 1]);
        }
    }

    __syncthreads();
    {
        int rl  = mg * 16 + (lane >> 2);
        int rl2 = rl + 8;
        #pragma unroll
        for (int nt = 0; nt < 8; nt++) {
            int colb = (ng * 64 + nt * 8 + (lane & 3) * 2) * 2;
            uint32_t b0 = pack_bf2(acc[nt][0], acc[nt][1]);
            uint32_t b1 = pack_bf2(acc[nt][2], acc[nt][3]);
            *reinterpret_cast<uint32_t*>(smem + P_OUT + rl  * 512 + (colb ^ ((rl  & 7) << 4))) = b0;
            *reinterpret_cast<uint32_t*>(smem + P_OUT + rl2 * 512 + (colb ^ ((rl2 & 7) << 4))) = b1;
        }
    }
    __syncthreads();
    {
        #pragma unroll
        for (int i = 0; i < 4; i++) {
            int idx = t + 512 * i;
            int row = idx >> 5, c16 = idx & 31;
            int gr = v0 + row;
            if (gr < V) {
                uint4 val = *reinterpret_cast<uint4*>(
                    smem + P_OUT + row * 512 + ((c16 * 16) ^ ((row & 7) << 4)));
                __nv_bfloat16* table = (c16 < 16) ? g_EKbf : g_EVbf;
                reinterpret_cast<uint4*>(table + (size_t)gr * DIM)[c16 & 15] = val;
            }
        }
    }
}

// ------------------------- K2: fused attention (writes output directly) ------
__global__ void __launch_bounds__(256) k_attn(const int* __restrict__ keys,
                                              const float* __restrict__ bk,
                                              float* __restrict__ outp,
                                              int L2, int M) {
    const int t      = threadIdx.x;
    const int w      = t >> 5;
    const int lane   = t & 31;
    const int lane16 = lane & 15;
    const int sel    = lane >> 4;
    const int bl     = blockIdx.x * 8 + w;

    __shared__ uint2 s_km[8][52];       // {byte offset kid*256, mask as float}

    if (bl < M) {
        for (int i = lane; i < 52; i += 32) {
            uint2 v = make_uint2(0u, 0u);
            if (i < L2) {
                int kid = keys[bl * L2 + i];
                float m = (g_Esum[kid] == 0.0f) ? 0.0f : 1.0f;
                v = make_uint2((uint32_t)kid << 8, __float_as_uint(m));
            }
            s_km[w][i] = v;
        }
    }
    __syncwarp();
    if (bl >= M) return;

    const float4* qp  = reinterpret_cast<const float4*>(g_Q + (size_t)bl * DIM + lane16 * 8);
    const float4* bkp = reinterpret_cast<const float4*>(bk + lane16 * 8);
    const float4 qa = qp[0], qb = qp[1];
    const float4 ba = bkp[0], bb = bkp[1];
    float corrp = qa.x * ba.x + qa.y * ba.y + qa.z * ba.z + qa.w * ba.w
                + qb.x * bb.x + qb.y * bb.y + qb.z * bb.z + qb.w * bb.w;

    const float RS = 0.17677669529663687f;   // 1/sqrt(32)
    const char* ekb = reinterpret_cast<const char*>(g_EKbf);
    const char* evb = reinterpret_cast<const char*>(g_EVbf);
    const uint32_t lo16 = lane16 * 16;

    float a0 = 0.f, a1 = 0.f, a2 = 0.f, a3 = 0.f;
    float a4 = 0.f, a5 = 0.f, a6 = 0.f, a7 = 0.f;
    float sumw = 0.f;

    const int np = (L2 + 3) >> 2;
    for (int i = 0; i < np; i++) {
        uint2 km0 = s_km[w][4 * i + sel];
        uint2 km1 = s_km[w][4 * i + 2 + sel];
        uint4 kr0 = *reinterpret_cast<const uint4*>(ekb + km0.x + lo16);
        uint4 kr1 = *reinterpret_cast<const uint4*>(ekb + km1.x + lo16);
        uint4 vr0 = *reinterpret_cast<const uint4*>(evb + km0.x + lo16);
        uint4 vr1 = *reinterpret_cast<const uint4*>(evb + km1.x + lo16);
        float p0 = corrp, p1 = corrp;
        p0 = fmaf(qa.x, bflo(kr0.x), p0); p1 = fmaf(qa.x, bflo(kr1.x), p1);
        p0 = fmaf(qa.y, bfhi(kr0.x), p0); p1 = fmaf(qa.y, bfhi(kr1.x), p1);
        p0 = fmaf(qa.z, bflo(kr0.y), p0); p1 = fmaf(qa.z, bflo(kr1.y), p1);
        p0 = fmaf(qa.w, bfhi(kr0.y), p0); p1 = fmaf(qa.w, bfhi(kr1.y), p1);
        p0 = fmaf(qb.x, bflo(kr0.z), p0); p1 = fmaf(qb.x, bflo(kr1.z), p1);
        p0 = fmaf(qb.y, bfhi(kr0.z), p0); p1 = fmaf(qb.y, bfhi(kr1.z), p1);
        p0 = fmaf(qb.z, bflo(kr0.w), p0); p1 = fmaf(qb.z, bflo(kr1.w), p1);
        p0 = fmaf(qb.w, bfhi(kr0.w), p0); p1 = fmaf(qb.w, bfhi(kr1.w), p1);
        p0 += __shfl_xor_sync(0xffffffffu, p0, 1);
        p1 += __shfl_xor_sync(0xffffffffu, p1, 1);
        p0 += __shfl_xor_sync(0xffffffffu, p0, 2);
        p1 += __shfl_xor_sync(0xffffffffu, p1, 2);
        float w0 = __uint_as_float(km0.y) * __expf(p0 * RS);
        float w1 = __uint_as_float(km1.y) * __expf(p1 * RS);
        a0 = fmaf(w0, bflo(vr0.x), a0); a0 = fmaf(w1, bflo(vr1.x), a0);
        a1 = fmaf(w0, bfhi(vr0.x), a1); a1 = fmaf(w1, bfhi(vr1.x), a1);
        a2 = fmaf(w0, bflo(vr0.y), a2); a2 = fmaf(w1, bflo(vr1.y), a2);
        a3 = fmaf(w0, bfhi(vr0.y), a3); a3 = fmaf(w1, bfhi(vr1.y), a3);
        a4 = fmaf(w0, bflo(vr0.z), a4); a4 = fmaf(w1, bflo(vr1.z), a4);
        a5 = fmaf(w0, bfhi(vr0.z), a5); a5 = fmaf(w1, bfhi(vr1.z), a5);
        a6 = fmaf(w0, bflo(vr0.w), a6); a6 = fmaf(w1, bflo(vr1.w), a6);
        a7 = fmaf(w0, bfhi(vr0.w), a7); a7 = fmaf(w1, bfhi(vr1.w), a7);
        sumw += w0 + w1;
    }

    sumw += __shfl_xor_sync(0xffffffffu, sumw, 16);
    a0 += __shfl_xor_sync(0xffffffffu, a0, 16);
    a1 += __shfl_xor_sync(0xffffffffu, a1, 16);
    a2 += __shfl_xor_sync(0xffffffffu, a2, 16);
    a3 += __shfl_xor_sync(0xffffffffu, a3, 16);
    a4 += __shfl_xor_sync(0xffffffffu, a4, 16);
    a5 += __shfl_xor_sync(0xffffffffu, a5, 16);
    a6 += __shfl_xor_sync(0xffffffffu, a6, 16);
    a7 += __shfl_xor_sync(0xffffffffu, a7, 16);

    const float inv = 1.0f / sumw;
    const int   d0  = lane16 * 8 + sel * 4;
    const float4 qf = *reinterpret_cast<const float4*>(g_QF + (size_t)bl * DIM + d0);
    float4 o;
    if (sel == 0) {
        o.x = fmaf(a0, inv, qf.x);
        o.y = fmaf(a1, inv, qf.y);
        o.z = fmaf(a2, inv, qf.z);
        o.w = fmaf(a3, inv, qf.w);
    } else {
        o.x = fmaf(a4, inv, qf.x);
        o.y = fmaf(a5, inv, qf.y);
        o.z = fmaf(a6, inv, qf.z);
        o.w = fmaf(a7, inv, qf.w);
    }
    *reinterpret_cast<float4*>(outp + (size_t)bl * DIM + d0) = o;
}

// ------------------------- launch --------------------------------------------
extern "C" void kernel_launch(void* const* d_in, const int* in_sizes, int n_in,
                              void* d_out, int out_size) {
    const int*   queries = (const int*)d_in[0];
    const int*   keys    = (const int*)d_in[1];
    const float* E       = (const float*)d_in[2];
    const float* Wq      = (const float*)d_in[3];
    const float* bq      = (const float*)d_in[4];
    const float* Wk      = (const float*)d_in[5];
    const float* bk      = (const float*)d_in[6];
    const float* Wv      = (const float*)d_in[7];
    const float* bv      = (const float*)d_in[8];
    const float* Wf      = (const float*)d_in[9];
    const float* bf      = (const float*)d_in[10];
    float* out = (float*)d_out;

    const int V  = in_sizes[2] / DIM;
    const int M  = in_sizes[0];
    const int L2 = in_sizes[1] / M;

    cudaFuncSetAttribute(k_proj_mma, cudaFuncAttributeMaxDynamicSharedMemorySize, PROJ_SMEM);
    cudaFuncSetAttribute(k_wvf,      cudaFuncAttributeMaxDynamicSharedMemorySize, WVF_SMEM);

    const int nq    = (M + 63) / 64;       // 200 gather blocks (Q+QF combined)
    const int nproj = (V + 63) / 64;

    k_wvf<<<16, 256, WVF_SMEM>>>(Wv, Wf, bv, bf);
    k_wprep<<<24, 256>>>(Wk, Wq, Wf);
    k_proj_mma<<<nq + nproj, 512, PROJ_SMEM>>>(E, queries, bq, V, M, nq);
    k_attn<<<(M + 7) / 8, 256>>>(keys, bk, out, L2, M);
}

// round 17
// speedup vs baseline: 1.1728x; 1.1728x over previous
#include <cuda_runtime.h>
#include <cuda_bf16.h>
#include <cstdint>

#define VOCAB_MAX 100000
#define BL_MAX    12800
#define DIM       128
#define NHEAD     4

// ------------------------- scratch (device globals) -------------------------
__device__ __nv_bfloat16 g_EKbf[VOCAB_MAX * DIM];   // E @ Wk  (bf16)
__device__ __nv_bfloat16 g_EVbf[VOCAB_MAX * DIM];   // E @ Wv  (bf16)
__device__ float g_Esum[VOCAB_MAX];
__device__ float g_Q[BL_MAX * DIM];
__device__ float g_res[BL_MAX * DIM];
// swizzled fp16 W^T images (n-major, k contiguous, kc ^= n&7)
__device__ uint4 g_WT16[4096];   // [Wk|Wv]: [n=256][kc=16]
__device__ uint4 g_WQ16[2048];   // Wq:      [n=128][kc=16]
__device__ uint4 g_WF16[2048];   // Wf:      [n=128][kc=16]

// ------------------------- helpers ------------------------------------------
__device__ __forceinline__ uint32_t smem_to_u32(const void* p) {
    uint32_t a;
    asm("{ .reg .u64 t; cvta.to.shared.u64 t, %1; cvt.u32.u64 %0, t; }" : "=r"(a) : "l"(p));
    return a;
}
__device__ __forceinline__ uint32_t pack_bf2(float lo, float hi) {
    uint32_t r; asm("cvt.rn.bf16x2.f32 %0, %1, %2;" : "=r"(r) : "f"(hi), "f"(lo)); return r;
}
__device__ __forceinline__ uint32_t pack_h2(float lo, float hi) {
    uint32_t r; asm("cvt.rn.f16x2.f32 %0, %1, %2;" : "=r"(r) : "f"(hi), "f"(lo)); return r;
}
__device__ __forceinline__ void ldsm_x4(uint32_t addr, uint32_t* r) {
    asm volatile("ldmatrix.sync.aligned.m8n8.x4.shared.b16 {%0,%1,%2,%3}, [%4];"
                 : "=r"(r[0]), "=r"(r[1]), "=r"(r[2]), "=r"(r[3]) : "r"(addr));
}
__device__ __forceinline__ void mma_f16(float* c, const uint32_t* a, uint32_t b0, uint32_t b1) {
    asm volatile("mma.sync.aligned.m16n8k16.row.col.f32.f16.f16.f32 "
                 "{%0,%1,%2,%3}, {%4,%5,%6,%7}, {%8,%9}, {%0,%1,%2,%3};"
                 : "+f"(c[0]), "+f"(c[1]), "+f"(c[2]), "+f"(c[3])
                 : "r"(a[0]), "r"(a[1]), "r"(a[2]), "r"(a[3]), "r"(b0), "r"(b1));
}
__device__ __forceinline__ float bflo(uint32_t u) { return __uint_as_float(u << 16); }
__device__ __forceinline__ float bfhi(uint32_t u) { return __uint_as_float(u & 0xffff0000u); }

// ------------------------- K0: prep all W^T fp16 images ----------------------
__global__ void k_wprep(const float* __restrict__ Wk, const float* __restrict__ Wv,
                        const float* __restrict__ Wq, const float* __restrict__ Wf) {
    int u = blockIdx.x * blockDim.x + threadIdx.x;    // 8192 units
    const float* src;
    int n, kc;
    uint4* dst;
    if (u < 4096) {
        n = u & 255; kc = u >> 8;
        src = (n < 128) ? (Wk + n) : (Wv + (n - 128));
        dst = g_WT16 + n * 16 + (kc ^ (n & 7));
    } else if (u < 6144) {
        int u2 = u - 4096; n = u2 & 127; kc = u2 >> 7;
        src = Wq + n;
        dst = g_WQ16 + n * 16 + (kc ^ (n & 7));
    } else {
        int u2 = u - 6144; n = u2 & 127; kc = u2 >> 7;
        src = Wf + n;
        dst = g_WF16 + n * 16 + (kc ^ (n & 7));
    }
    float f[8];
    #pragma unroll
    for (int i = 0; i < 8; i++) f[i] = src[(size_t)(kc * 8 + i) * DIM];
    uint32_t h[4];
    #pragma unroll
    for (int i = 0; i < 4; i++) h[i] = pack_h2(f[2 * i], f[2 * i + 1]);
    *dst = make_uint4(h[0], h[1], h[2], h[3]);
}

// ------------------------- K1: fused proj + Q gemm ---------------------------
// Blocks [0, nq): Q = gather(E,queries)@Wq + bq (fp16, M=128 x N=128)
// Blocks [nq, ...): EK|EV = E @ [Wk|Wv]        (fp16, M=64  x N=256)
#define P_A   0
#define P_B   16384
#define P_OUT 81920
#define Q_A   0
#define Q_B   32768
#define PROJ_SMEM 114688

__device__ void gemm_q_path(char* smem, uint32_t sb,
                            const float* __restrict__ E,
                            const int* __restrict__ queries,
                            const float* __restrict__ bq, int M, int bx) {
    const int t    = threadIdx.x;
    const int w    = t >> 5;
    const int lane = t & 31;
    const int m0   = bx * 128;

    #pragma unroll
    for (int i = 0; i < 4; i++) {
        int u   = t + 512 * i;
        int row = u >> 4;
        int kc  = u & 15;
        int m   = m0 + row;
        int mm  = (m < M) ? m : 0;
        const float4* src = reinterpret_cast<const float4*>(E + (size_t)queries[mm] * DIM + kc * 8);
        float4 f0 = src[0], f1 = src[1];
        uint32_t h0 = pack_h2(f0.x, f0.y), h1 = pack_h2(f0.z, f0.w);
        uint32_t h2 = pack_h2(f1.x, f1.y), h3 = pack_h2(f1.z, f1.w);
        uint32_t off = (uint32_t)row * 256 + (uint32_t)((kc ^ (row & 7)) << 4);
        *reinterpret_cast<uint4*>(smem + Q_A + off) = make_uint4(h0, h1, h2, h3);
    }
    {
        uint4* d = reinterpret_cast<uint4*>(smem + Q_B);
        #pragma unroll
        for (int i = 0; i < 4; i++) {
            int idx = t + 512 * i;
            d[idx] = g_WQ16[idx];
        }
    }
    __syncthreads();

    const int mg = w & 3;
    const int ng = w >> 2;

    float acc[2][4][4];
    #pragma unroll
    for (int mt = 0; mt < 2; mt++)
        #pragma unroll
        for (int nt = 0; nt < 4; nt++)
            #pragma unroll
            for (int j = 0; j < 4; j++) acc[mt][nt][j] = 0.f;

    const int aRow  = mg * 32 + ((lane >> 3) & 1) * 8 + (lane & 7);
    const int aKsel = (lane >> 4);
    const int bN    = ng * 32 + ((lane >> 4) & 1) * 8 + (lane & 7);
    const int bKsel = (lane >> 3) & 1;

    #pragma unroll
    for (int ks = 0; ks < 8; ks++) {
        uint32_t a[2][4];
        #pragma unroll
        for (int mt = 0; mt < 2; mt++) {
            int row = aRow + mt * 16;
            int kc  = ks * 2 + aKsel;
            ldsm_x4(sb + Q_A + row * 256 + (((kc ^ (row & 7)) << 4)), a[mt]);
        }
        uint32_t b[2][4];
        #pragma unroll
        for (int bt = 0; bt < 2; bt++) {
            int n  = bN + bt * 16;
            int kc = ks * 2 + bKsel;
            ldsm_x4(sb + Q_B + n * 256 + (((kc ^ (n & 7)) << 4)), b[bt]);
        }
        #pragma unroll
        for (int mt = 0; mt < 2; mt++)
            #pragma unroll
            for (int nt = 0; nt < 4; nt++)
                mma_f16(acc[mt][nt], a[mt], b[nt >> 1][(nt & 1) * 2], b[nt >> 1][(nt & 1) * 2 + 1]);
    }

    #pragma unroll
    for (int mt = 0; mt < 2; mt++) {
        int row = m0 + mg * 32 + mt * 16 + (lane >> 2);
        #pragma unroll
        for (int nt = 0; nt < 4; nt++) {
            int col = ng * 32 + nt * 8 + (lane & 3) * 2;
            float b0 = bq[col], b1 = bq[col + 1];
            if (row < M) {
                *reinterpret_cast<float2*>(g_Q + (size_t)row * DIM + col) =
                    make_float2(acc[mt][nt][0] + b0, acc[mt][nt][1] + b1);
                if (row + 8 < M)
                    *reinterpret_cast<float2*>(g_Q + (size_t)(row + 8) * DIM + col) =
                        make_float2(acc[mt][nt][2] + b0, acc[mt][nt][3] + b1);
            }
        }
    }
}

__global__ void __launch_bounds__(512, 2)
k_proj_mma(const float* __restrict__ E, const int* __restrict__ queries,
           const float* __restrict__ bq, int V, int M, int nq) {
    extern __shared__ char smem[];
    const uint32_t sb = smem_to_u32(smem);

    if ((int)blockIdx.x < nq) {
        gemm_q_path(smem, sb, E, queries, bq, M, blockIdx.x);
        return;
    }

    const int t    = threadIdx.x;
    const int w    = t >> 5;
    const int lane = t & 31;
    const int v0   = (blockIdx.x - nq) * 64;

    #pragma unroll
    for (int i = 0; i < 2; i++) {
        int u   = t + 512 * i;
        int row = u >> 4;
        int kc  = u & 15;
        int gr  = v0 + row;
        int grc = (gr < V) ? gr : 0;
        const float4* src = reinterpret_cast<const float4*>(E + (size_t)grc * DIM + kc * 8);
        float4 f0 = __ldcs(src);
        float4 f1 = __ldcs(src + 1);
        uint32_t h0 = pack_h2(f0.x, f0.y), h1 = pack_h2(f0.z, f0.w);
        uint32_t h2 = pack_h2(f1.x, f1.y), h3 = pack_h2(f1.z, f1.w);
        uint32_t off = (uint32_t)row * 256 + (uint32_t)((kc ^ (row & 7)) << 4);
        *reinterpret_cast<uint4*>(smem + P_A + off) = make_uint4(h0, h1, h2, h3);
        float s8 = ((f0.x + f0.y) + (f0.z + f0.w)) + ((f1.x + f1.y) + (f1.z + f1.w));
        s8 += __shfl_xor_sync(0xffffffffu, s8, 8);
        s8 += __shfl_xor_sync(0xffffffffu, s8, 4);
        s8 += __shfl_xor_sync(0xffffffffu, s8, 2);
        s8 += __shfl_xor_sync(0xffffffffu, s8, 1);
        if ((t & 15) == 0 && gr < V) g_Esum[gr] = s8;
    }
    {
        uint4* d = reinterpret_cast<uint4*>(smem + P_B);
        #pragma unroll
        for (int i = 0; i < 8; i++) {
            int idx = t + 512 * i;
            d[idx] = g_WT16[idx];
        }
    }
    __syncthreads();

    const int mg = w & 3;
    const int ng = w >> 2;

    float acc[8][4];
    #pragma unroll
    for (int nt = 0; nt < 8; nt++)
        #pragma unroll
        for (int j = 0; j < 4; j++) acc[nt][j] = 0.f;

    const int aRow  = mg * 16 + ((lane >> 3) & 1) * 8 + (lane & 7);
    const int aKsel = (lane >> 4);
    const int bN    = ng * 64 + ((lane >> 4) & 1) * 8 + (lane & 7);
    const int bKsel = (lane >> 3) & 1;

    #pragma unroll
    for (int ks = 0; ks < 8; ks++) {
        uint32_t a[4];
        {
            int kc = ks * 2 + aKsel;
            ldsm_x4(sb + P_A + aRow * 256 + (((kc ^ (aRow & 7)) << 4)), a);
        }
        {
            uint32_t b[2][4];
            #pragma unroll
            for (int bt = 0; bt < 2; bt++) {
                int n  = bN + bt * 16;
                int kc = ks * 2 + bKsel;
                ldsm_x4(sb + P_B + n * 256 + (((kc ^ (n & 7)) << 4)), b[bt]);
            }
            #pragma unroll
            for (int nt = 0; nt < 4; nt++)
                mma_f16(acc[nt], a, b[nt >> 1][(nt & 1) * 2], b[nt >> 1][(nt & 1) * 2 + 1]);
        }
        {
            uint32_t b[2][4];
            #pragma unroll
            for (int bt = 0; bt < 2; bt++) {
                int n  = bN + (bt + 2) * 16;
                int kc = ks * 2 + bKsel;
                ldsm_x4(sb + P_B + n * 256 + (((kc ^ (n & 7)) << 4)), b[bt]);
            }
            #pragma unroll
            for (int nt = 4; nt < 8; nt++)
                mma_f16(acc[nt], a, b[(nt - 4) >> 1][(nt & 1) * 2], b[(nt - 4) >> 1][(nt & 1) * 2 + 1]);
        }
    }

    __syncthreads();
    {
        int rl  = mg * 16 + (lane >> 2);
        int rl2 = rl + 8;
        #pragma unroll
        for (int nt = 0; nt < 8; nt++) {
            int colb = (ng * 64 + nt * 8 + (lane & 3) * 2) * 2;
            uint32_t b0 = pack_bf2(acc[nt][0], acc[nt][1]);
            uint32_t b1 = pack_bf2(acc[nt][2], acc[nt][3]);
            *reinterpret_cast<uint32_t*>(smem + P_OUT + rl  * 512 + (colb ^ ((rl  & 7) << 4))) = b0;
            *reinterpret_cast<uint32_t*>(smem + P_OUT + rl2 * 512 + (colb ^ ((rl2 & 7) << 4))) = b1;
        }
    }
    __syncthreads();
    {
        #pragma unroll
        for (int i = 0; i < 4; i++) {
            int idx = t + 512 * i;
            int row = idx >> 5, c16 = idx & 31;
            int gr = v0 + row;
            if (gr < V) {
                uint4 val = *reinterpret_cast<uint4*>(
                    smem + P_OUT + row * 512 + ((c16 * 16) ^ ((row & 7) << 4)));
                __nv_bfloat16* table = (c16 < 16) ? g_EKbf : g_EVbf;
                reinterpret_cast<uint4*>(table + (size_t)gr * DIM)[c16 & 15] = val;
            }
        }
    }
}

// ------------------------- K2b: final gemm (fp16, M=32, 4 CTA/SM) ------------
// 256 threads, 8 warps (warp tile 16x32), smem 40KB, short chain, grid 400.
#define F_A 0
#define F_B 8192
#define GEMMF_SMEM 40960

__global__ void __launch_bounds__(256, 4)
k_gemm_f(const float* __restrict__ bf, float* __restrict__ outp, int M) {
    extern __shared__ char smem[];
    const uint32_t sb = smem_to_u32(smem);
    const int t    = threadIdx.x;
    const int w    = t >> 5;
    const int lane = t & 31;
    const int m0   = blockIdx.x * 32;

    // stage A (fp16): 32 rows x 16 kc = 512 units
    #pragma unroll
    for (int i = 0; i < 2; i++) {
        int u   = t + 256 * i;
        int row = u >> 4;
        int kc  = u & 15;
        int m   = m0 + row;
        const float4* src = reinterpret_cast<const float4*>(
            g_res + (size_t)((m < M) ? m : 0) * DIM + kc * 8);
        float4 f0 = src[0], f1 = src[1];
        uint32_t h0 = pack_h2(f0.x, f0.y), h1 = pack_h2(f0.z, f0.w);
        uint32_t h2 = pack_h2(f1.x, f1.y), h3 = pack_h2(f1.z, f1.w);
        uint32_t off = (uint32_t)row * 256 + (uint32_t)((kc ^ (row & 7)) << 4);
        *reinterpret_cast<uint4*>(smem + F_A + off) = make_uint4(h0, h1, h2, h3);
    }
    // stage B: fp16 Wf image (32KB)
    {
        uint4* d = reinterpret_cast<uint4*>(smem + F_B);
        #pragma unroll
        for (int i = 0; i < 8; i++) {
            int idx = t + 256 * i;
            d[idx] = g_WF16[idx];
        }
    }
    __syncthreads();

    const int mg = w & 1;        // 2 row groups of 16
    const int ng = w >> 1;       // 4 col groups of 32

    float acc[4][4];
    #pragma unroll
    for (int nt = 0; nt < 4; nt++)
        #pragma unroll
        for (int j = 0; j < 4; j++) acc[nt][j] = 0.f;

    const int aRow  = mg * 16 + ((lane >> 3) & 1) * 8 + (lane & 7);
    const int aKsel = (lane >> 4);
    const int bN    = ng * 32 + ((lane >> 4) & 1) * 8 + (lane & 7);
    const int bKsel = (lane >> 3) & 1;

    #pragma unroll
    for (int ks = 0; ks < 8; ks++) {
        uint32_t a[4];
        {
            int kc = ks * 2 + aKsel;
            ldsm_x4(sb + F_A + aRow * 256 + (((kc ^ (aRow & 7)) << 4)), a);
        }
        uint32_t b[2][4];
        #pragma unroll
        for (int bt = 0; bt < 2; bt++) {
            int n  = bN + bt * 16;
            int kc = ks * 2 + bKsel;
            ldsm_x4(sb + F_B + n * 256 + (((kc ^ (n & 7)) << 4)), b[bt]);
        }
        #pragma unroll
        for (int nt = 0; nt < 4; nt++)
            mma_f16(acc[nt], a, b[nt >> 1][(nt & 1) * 2], b[nt >> 1][(nt & 1) * 2 + 1]);
    }

    {
        int row = m0 + mg * 16 + (lane >> 2);
        #pragma unroll
        for (int nt = 0; nt < 4; nt++) {
            int col = ng * 32 + nt * 8 + (lane & 3) * 2;
            float b0 = bf[col], b1 = bf[col + 1];
            if (row < M)
                *reinterpret_cast<float2*>(outp + (size_t)row * DIM + col) =
                    make_float2(acc[nt][0] + b0, acc[nt][1] + b1);
            if (row + 8 < M)
                *reinterpret_cast<float2*>(outp + (size_t)(row + 8) * DIM + col) =
                    make_float2(acc[nt][2] + b0, acc[nt][3] + b1);
        }
    }
}

// ------------------------- K3: fused attention, warp per (b,l), dual chain ---
__global__ void __launch_bounds__(256) k_attn(const int* __restrict__ queries,
                                              const int* __restrict__ keys,
                                              const float* __restrict__ E,
                                              const float* __restrict__ bk,
                                              const float* __restrict__ bv,
                                              int L2, int M) {
    const int t      = threadIdx.x;
    const int w      = t >> 5;
    const int lane   = t & 31;
    const int lane16 = lane & 15;
    const int sel    = lane >> 4;
    const int bl     = blockIdx.x * 8 + w;

    __shared__ uint2 s_km[8][52];       // {byte offset kid*256, mask as float}

    if (bl < M) {
        for (int i = lane; i < 52; i += 32) {
            uint2 v = make_uint2(0u, 0u);
            if (i < L2) {
                int kid = keys[bl * L2 + i];
                float m = (g_Esum[kid] == 0.0f) ? 0.0f : 1.0f;
                v = make_uint2((uint32_t)kid << 8, __float_as_uint(m));
            }
            s_km[w][i] = v;
        }
    }
    __syncwarp();
    if (bl >= M) return;

    const float4* qp  = reinterpret_cast<const float4*>(g_Q + (size_t)bl * DIM + lane16 * 8);
    const float4* bkp = reinterpret_cast<const float4*>(bk + lane16 * 8);
    const float4 qa = qp[0], qb = qp[1];
    const float4 ba = bkp[0], bb = bkp[1];
    float corrp = qa.x * ba.x + qa.y * ba.y + qa.z * ba.z + qa.w * ba.w
                + qb.x * bb.x + qb.y * bb.y + qb.z * bb.z + qb.w * bb.w;

    const float RS = 0.17677669529663687f;   // 1/sqrt(32)
    const char* ekb = reinterpret_cast<const char*>(g_EKbf);
    const char* evb = reinterpret_cast<const char*>(g_EVbf);
    const uint32_t lo16 = lane16 * 16;

    float a0 = 0.f, a1 = 0.f, a2 = 0.f, a3 = 0.f;
    float a4 = 0.f, a5 = 0.f, a6 = 0.f, a7 = 0.f;
    float sumw = 0.f;

    const int np = (L2 + 3) >> 2;
    for (int i = 0; i < np; i++) {
        uint2 km0 = s_km[w][4 * i + sel];
        uint2 km1 = s_km[w][4 * i + 2 + sel];
        uint4 kr0 = *reinterpret_cast<const uint4*>(ekb + km0.x + lo16);
        uint4 kr1 = *reinterpret_cast<const uint4*>(ekb + km1.x + lo16);
        uint4 vr0 = *reinterpret_cast<const uint4*>(evb + km0.x + lo16);
        uint4 vr1 = *reinterpret_cast<const uint4*>(evb + km1.x + lo16);
        float p0 = corrp, p1 = corrp;
        p0 = fmaf(qa.x, bflo(kr0.x), p0); p1 = fmaf(qa.x, bflo(kr1.x), p1);
        p0 = fmaf(qa.y, bfhi(kr0.x), p0); p1 = fmaf(qa.y, bfhi(kr1.x), p1);
        p0 = fmaf(qa.z, bflo(kr0.y), p0); p1 = fmaf(qa.z, bflo(kr1.y), p1);
        p0 = fmaf(qa.w, bfhi(kr0.y), p0); p1 = fmaf(qa.w, bfhi(kr1.y), p1);
        p0 = fmaf(qb.x, bflo(kr0.z), p0); p1 = fmaf(qb.x, bflo(kr1.z), p1);
        p0 = fmaf(qb.y, bfhi(kr0.z), p0); p1 = fmaf(qb.y, bfhi(kr1.z), p1);
        p0 = fmaf(qb.z, bflo(kr0.w), p0); p1 = fmaf(qb.z, bflo(kr1.w), p1);
        p0 = fmaf(qb.w, bfhi(kr0.w), p0); p1 = fmaf(qb.w, bfhi(kr1.w), p1);
        p0 += __shfl_xor_sync(0xffffffffu, p0, 1);
        p1 += __shfl_xor_sync(0xffffffffu, p1, 1);
        p0 += __shfl_xor_sync(0xffffffffu, p0, 2);
        p1 += __shfl_xor_sync(0xffffffffu, p1, 2);
        float w0 = __uint_as_float(km0.y) * __expf(p0 * RS);
        float w1 = __uint_as_float(km1.y) * __expf(p1 * RS);
        a0 = fmaf(w0, bflo(vr0.x), a0); a0 = fmaf(w1, bflo(vr1.x), a0);
        a1 = fmaf(w0, bfhi(vr0.x), a1); a1 = fmaf(w1, bfhi(vr1.x), a1);
        a2 = fmaf(w0, bflo(vr0.y), a2); a2 = fmaf(w1, bflo(vr1.y), a2);
        a3 = fmaf(w0, bfhi(vr0.y), a3); a3 = fmaf(w1, bfhi(vr1.y), a3);
        a4 = fmaf(w0, bflo(vr0.z), a4); a4 = fmaf(w1, bflo(vr1.z), a4);
        a5 = fmaf(w0, bfhi(vr0.z), a5); a5 = fmaf(w1, bfhi(vr1.z), a5);
        a6 = fmaf(w0, bflo(vr0.w), a6); a6 = fmaf(w1, bflo(vr1.w), a6);
        a7 = fmaf(w0, bfhi(vr0.w), a7); a7 = fmaf(w1, bfhi(vr1.w), a7);
        sumw += w0 + w1;
    }

    sumw += __shfl_xor_sync(0xffffffffu, sumw, 16);
    a0 += __shfl_xor_sync(0xffffffffu, a0, 16);
    a1 += __shfl_xor_sync(0xffffffffu, a1, 16);
    a2 += __shfl_xor_sync(0xffffffffu, a2, 16);
    a3 += __shfl_xor_sync(0xffffffffu, a3, 16);
    a4 += __shfl_xor_sync(0xffffffffu, a4, 16);
    a5 += __shfl_xor_sync(0xffffffffu, a5, 16);
    a6 += __shfl_xor_sync(0xffffffffu, a6, 16);
    a7 += __shfl_xor_sync(0xffffffffu, a7, 16);

    const float inv = 1.0f / sumw;
    const int   qid = queries[bl];
    const int   d0  = lane16 * 8 + sel * 4;
    const float4 bv4 = *reinterpret_cast<const float4*>(bv + d0);
    const float4 qe4 = *reinterpret_cast<const float4*>(E + (size_t)qid * DIM + d0);
    float4 o;
    if (sel == 0) {
        o.x = fmaf(a0, inv, bv4.x + qe4.x);
        o.y = fmaf(a1, inv, bv4.y + qe4.y);
        o.z = fmaf(a2, inv, bv4.z + qe4.z);
        o.w = fmaf(a3, inv, bv4.w + qe4.w);
    } else {
        o.x = fmaf(a4, inv, bv4.x + qe4.x);
        o.y = fmaf(a5, inv, bv4.y + qe4.y);
        o.z = fmaf(a6, inv, bv4.z + qe4.z);
        o.w = fmaf(a7, inv, bv4.w + qe4.w);
    }
    *reinterpret_cast<float4*>(g_res + (size_t)bl * DIM + d0) = o;
}

// ------------------------- launch --------------------------------------------
extern "C" void kernel_launch(void* const* d_in, const int* in_sizes, int n_in,
                              void* d_out, int out_size) {
    const int*   queries = (const int*)d_in[0];
    const int*   keys    = (const int*)d_in[1];
    const float* E       = (const float*)d_in[2];
    const float* Wq      = (const float*)d_in[3];
    const float* bq      = (const float*)d_in[4];
    const float* Wk      = (const float*)d_in[5];
    const float* bk      = (const float*)d_in[6];
    const float* Wv      = (const float*)d_in[7];
    const float* bv      = (const float*)d_in[8];
    const float* Wf      = (const float*)d_in[9];
    const float* bf      = (const float*)d_in[10];
    float* out = (float*)d_out;

    const int V  = in_sizes[2] / DIM;
    const int M  = in_sizes[0];
    const int L2 = in_sizes[1] / M;

    cudaFuncSetAttribute(k_proj_mma, cudaFuncAttributeMaxDynamicSharedMemorySize, PROJ_SMEM);
    cudaFuncSetAttribute(k_gemm_f,   cudaFuncAttributeMaxDynamicSharedMemorySize, GEMMF_SMEM);

    const int nq    = (M + 127) / 128;
    const int nproj = (V + 63) / 64;

    k_wprep<<<32, 256>>>(Wk, Wv, Wq, Wf);
    k_proj_mma<<<nq + nproj, 512, PROJ_SMEM>>>(E, queries, bq, V, M, nq);
    k_attn<<<(M + 7) / 8, 256>>>(queries, keys, E, bk, bv, L2, M);
    k_gemm_f<<<(M + 31) / 32, 256, GEMMF_SMEM>>>(bf, out, M);
}